// round 4
// baseline (speedup 1.0000x reference)
#include <cuda_runtime.h>
#include <math_constants.h>

#define NPTS 1024
#define HA   256

// ---------------- persistent device scratch ----------------
__device__ float g_qa[NPTS * HA];    // qa'[i][n] = (x@Wq)@aW1 + ab1 + pb2@aW1
__device__ float g_ka[NPTS * HA];    // ka[j][n]  = (x@Wk)@aW1
__device__ float g_vp[NPTS * 64];    // v'[j][d]  = x@Wv + pb2
__device__ float g_pW2a[64 * HA];    // pW2 @ aW1

// ---------------- f32x2 helpers (FFMA2 — PTX-only on sm_103a) ----------------
__device__ __forceinline__ unsigned long long ffma2(unsigned long long a, unsigned long long b, unsigned long long c) {
    unsigned long long d;
    asm("fma.rn.f32x2 %0, %1, %2, %3;" : "=l"(d) : "l"(a), "l"(b), "l"(c));
    return d;
}
__device__ __forceinline__ unsigned long long pack2(float lo, float hi) {
    unsigned long long r;
    asm("mov.b64 %0, {%1, %2};" : "=l"(r) : "f"(lo), "f"(hi));
    return r;
}
__device__ __forceinline__ void unpack2(unsigned long long v, float& lo, float& hi) {
    asm("mov.b64 {%0, %1}, %2;" : "=f"(lo), "=f"(hi) : "l"(v));
}

// ---------------- P0: pW2a = pW2 @ aW1 ----------------
__global__ void prep_pw2a(const float* __restrict__ pW2, const float* __restrict__ aW1) {
    int k = blockIdx.x;     // 0..63
    int n = threadIdx.x;    // 0..255
    float s = 0.f;
    #pragma unroll 16
    for (int c = 0; c < 64; ++c) s = fmaf(pW2[k * 64 + c], aW1[c * 256 + n], s);
    g_pW2a[k * 256 + n] = s;
}

// ---------------- P1: projections + folded biases ----------------
__global__ void prep_qkv(const float* __restrict__ x,  const float* __restrict__ Wq,
                         const float* __restrict__ Wk, const float* __restrict__ Wv,
                         const float* __restrict__ aW1, const float* __restrict__ ab1,
                         const float* __restrict__ pb2) {
    __shared__ float sx[64], sq[64], sk[64];
    int i = blockIdx.x, t = threadIdx.x;
    if (t < 64) sx[t] = x[i * 64 + t];
    __syncthreads();
    if (t < 64) {
        float aq = 0.f, ak = 0.f, av = 0.f;
        #pragma unroll 16
        for (int c = 0; c < 64; ++c) {
            float xc = sx[c];
            aq = fmaf(xc, Wq[c * 64 + t], aq);
            ak = fmaf(xc, Wk[c * 64 + t], ak);
            av = fmaf(xc, Wv[c * 64 + t], av);
        }
        sq[t] = aq; sk[t] = ak;
        g_vp[i * 64 + t] = av + pb2[t];
    }
    __syncthreads();
    int n = t; // 0..255
    float accq = 0.f, acck = 0.f, accb = 0.f;
    #pragma unroll 8
    for (int c = 0; c < 64; ++c) {
        float w = aW1[c * 256 + n];
        accq = fmaf(sq[c], w, accq);
        acck = fmaf(sk[c], w, acck);
        accb = fmaf(pb2[c], w, accb);
    }
    g_qa[i * HA + n] = accq + ab1[n] + accb;
    g_ka[i * HA + n] = acck;
}

// ---------------- main fused kernel: one CTA per query i ----------------
// smem float offsets
#define OFF_W2A 0u        // 64k x 256n row-major
#define OFF_AW2 16384u    // 256n x 64d row-major
#define OFF_PW2 32768u    // 64k x 64d row-major
#define OFF_H   36864u    // 64k x 68j (k-major, stride 68 keeps 16B align per row)
#define OFF_HID 41216u    // 16384 floats: hiddenT[256n][64j]; after S4: partials[2seg][64j][68]
#define OFF_PW1 57600u    // 128
#define OFF_PB1 57728u    // 64
#define SMEM_FLOATS 57792u
#define SMEM_BYTES  (SMEM_FLOATS * 4u)   // 231168 B

extern __shared__ float smem[];

__global__ __launch_bounds__(512, 1)
void pt_main(const float* __restrict__ pos, const float* __restrict__ pW1,
             const float* __restrict__ pb1, const float* __restrict__ pW2,
             const float* __restrict__ aW2, float* __restrict__ out) {
    const int i   = blockIdx.x;
    const int tid = threadIdx.x;

    float* sW2a = smem + OFF_W2A;
    float* sAW2 = smem + OFF_AW2;
    float* sPW2 = smem + OFF_PW2;
    float* sH   = smem + OFF_H;
    float* sHid = smem + OFF_HID;
    float* sPW1 = smem + OFF_PW1;
    float* sPb1 = smem + OFF_PB1;

    // ---- stage weights ----
    for (int idx = tid; idx < 64 * 256; idx += 512) sW2a[idx] = g_pW2a[idx];
    for (int idx = tid; idx < 256 * 64; idx += 512) sAW2[idx] = aW2[idx];
    for (int idx = tid; idx < 64 * 64;  idx += 512) sPW2[idx] = pW2[idx];
    if (tid < 128) sPW1[tid] = pW1[tid];
    if (tid < 64)  sPb1[tid] = pb1[tid];

    const float pix = __ldg(pos + i * 2 + 0);
    const float piy = __ldg(pos + i * 2 + 1);

    // ---- phase mappings ----
    const int lane  = tid & 31;
    const int warp  = tid >> 5;
    // A: j = tid&63, k-sub = tid>>6
    const int jA  = tid & 63;
    const int kA0 = tid >> 6;
    // B: lane owns j-pair {2*lane, 2*lane+1}; warp owns n-block [warp*16, +16)
    const int j0B = lane * 2;
    const int nbB = warp * 16;
    // C: warp = jh(1b) x dq(2b) x seg(1b); lane owns one j
    const int segC = warp >> 3;           // K-half: n in [segC*128, +128)
    const int dqC  = (warp >> 1) & 3;     // d-block [dqC*16, +16)
    const int jC   = (warp & 1) * 32 + lane;
    // E: channel + j-group
    const int d_e  = tid & 63;
    const int jsub = tid >> 6;
    const int j0E  = jsub * 8;

    // qa is chunk-invariant: hoist into registers (16 n values for phase B epilogue)
    float4 qreg[4];
    #pragma unroll
    for (int q = 0; q < 4; ++q)
        qreg[q] = __ldg(reinterpret_cast<const float4*>(g_qa + i * 256 + nbB + q * 4));

    float m_run = -CUDART_INF_F, l_run = 0.f, num_run = 0.f;

    for (int c = 0; c < 16; ++c) {
        const int jbase = c * 64;
        __syncthreads();   // S1: prev phase E done with sH/sHid (chunk0: staging done)

        // ---- Phase A: H[k][j] = relu(dx*pW1[0,k] + dy*pW1[1,k] + pb1[k]), k-major ----
        {
            float2 pj = *reinterpret_cast<const float2*>(pos + (jbase + jA) * 2);
            float dx = pix - pj.x, dy = piy - pj.y;
            #pragma unroll
            for (int p = 0; p < 8; ++p) {
                int k = p * 8 + kA0;
                float h = fmaxf(fmaf(dx, sPW1[k], fmaf(dy, sPW1[64 + k], sPb1[k])), 0.f);
                sH[k * 68 + jA] = h;
            }
        }
        __syncthreads();   // S2: H ready

        // ---- Phase B: hiddenT[n][j] = relu(qa - ka + H@pW2a) ----
        // lane: j-pair, warp: 16-n block. Weight LDS.128s are warp-uniform (broadcast).
        {
            unsigned long long accB[2][8];
            #pragma unroll
            for (int jj = 0; jj < 2; ++jj)
                #pragma unroll
                for (int g = 0; g < 8; ++g) accB[jj][g] = 0ull;

            #pragma unroll 4
            for (int k = 0; k < 64; ++k) {
                float2 hv = *reinterpret_cast<const float2*>(sH + k * 68 + j0B);
                unsigned long long hp0 = pack2(hv.x, hv.x);
                unsigned long long hp1 = pack2(hv.y, hv.y);
                const ulonglong2* wr = reinterpret_cast<const ulonglong2*>(sW2a + k * 256 + nbB);
                ulonglong2 w0 = wr[0], w1 = wr[1], w2 = wr[2], w3 = wr[3];
                accB[0][0] = ffma2(hp0, w0.x, accB[0][0]);
                accB[0][1] = ffma2(hp0, w0.y, accB[0][1]);
                accB[0][2] = ffma2(hp0, w1.x, accB[0][2]);
                accB[0][3] = ffma2(hp0, w1.y, accB[0][3]);
                accB[0][4] = ffma2(hp0, w2.x, accB[0][4]);
                accB[0][5] = ffma2(hp0, w2.y, accB[0][5]);
                accB[0][6] = ffma2(hp0, w3.x, accB[0][6]);
                accB[0][7] = ffma2(hp0, w3.y, accB[0][7]);
                accB[1][0] = ffma2(hp1, w0.x, accB[1][0]);
                accB[1][1] = ffma2(hp1, w0.y, accB[1][1]);
                accB[1][2] = ffma2(hp1, w1.x, accB[1][2]);
                accB[1][3] = ffma2(hp1, w1.y, accB[1][3]);
                accB[1][4] = ffma2(hp1, w2.x, accB[1][4]);
                accB[1][5] = ffma2(hp1, w2.y, accB[1][5]);
                accB[1][6] = ffma2(hp1, w3.x, accB[1][6]);
                accB[1][7] = ffma2(hp1, w3.y, accB[1][7]);
            }

            // epilogue: + qa - ka, relu, store transposed (j-contiguous pairs)
            float val[2][16];
            #pragma unroll
            for (int jj = 0; jj < 2; ++jj) {
                const int gj = jbase + j0B + jj;
                #pragma unroll
                for (int q = 0; q < 4; ++q) {
                    float4 ka4 = __ldg(reinterpret_cast<const float4*>(g_ka + (size_t)gj * 256 + nbB + q * 4));
                    float a0, a1, a2, a3;
                    unpack2(accB[jj][q * 2 + 0], a0, a1);
                    unpack2(accB[jj][q * 2 + 1], a2, a3);
                    val[jj][q * 4 + 0] = fmaxf(a0 + qreg[q].x - ka4.x, 0.f);
                    val[jj][q * 4 + 1] = fmaxf(a1 + qreg[q].y - ka4.y, 0.f);
                    val[jj][q * 4 + 2] = fmaxf(a2 + qreg[q].z - ka4.z, 0.f);
                    val[jj][q * 4 + 3] = fmaxf(a3 + qreg[q].w - ka4.w, 0.f);
                }
            }
            #pragma unroll
            for (int nn = 0; nn < 16; ++nn) {
                unsigned long long p = pack2(val[0][nn], val[1][nn]);
                *reinterpret_cast<unsigned long long*>(sHid + (nbB + nn) * 64 + j0B) = p;
            }
        }
        __syncthreads();   // S3: hiddenT ready

        // ---- Phase C: sim[j][d] = hiddenT^T @ aW2, K split in 2 segs ----
        // lane: 1 j, warp: 16-d block + K-half. Weight LDS.128s warp-uniform.
        unsigned long long accC[8];
        {
            #pragma unroll
            for (int z = 0; z < 8; ++z) accC[z] = 0ull;
            const int nb0 = segC * 128;
            #pragma unroll 4
            for (int nn = 0; nn < 128; ++nn) {
                const int n = nb0 + nn;
                float hv = sHid[n * 64 + jC];
                unsigned long long hp = pack2(hv, hv);
                const ulonglong2* wr = reinterpret_cast<const ulonglong2*>(sAW2 + n * 64 + dqC * 16);
                ulonglong2 w0 = wr[0], w1 = wr[1], w2 = wr[2], w3 = wr[3];
                accC[0] = ffma2(hp, w0.x, accC[0]);
                accC[1] = ffma2(hp, w0.y, accC[1]);
                accC[2] = ffma2(hp, w1.x, accC[2]);
                accC[3] = ffma2(hp, w1.y, accC[3]);
                accC[4] = ffma2(hp, w2.x, accC[4]);
                accC[5] = ffma2(hp, w2.y, accC[5]);
                accC[6] = ffma2(hp, w3.x, accC[6]);
                accC[7] = ffma2(hp, w3.y, accC[7]);
            }
        }
        __syncthreads();   // S4: all hiddenT reads done — safe to overwrite with partials

        // partials: [seg][j][68] (stride 68 avoids 32-way store conflict)
        {
            float* part = sHid + segC * 4352 + jC * 68 + dqC * 16;
            ulonglong2 t0, t1;
            t0.x = accC[0]; t0.y = accC[1];
            t1.x = accC[2]; t1.y = accC[3];
            reinterpret_cast<ulonglong2*>(part)[0] = t0;
            reinterpret_cast<ulonglong2*>(part)[1] = t1;
            t0.x = accC[4]; t0.y = accC[5];
            t1.x = accC[6]; t1.y = accC[7];
            reinterpret_cast<ulonglong2*>(part)[2] = t0;
            reinterpret_cast<ulonglong2*>(part)[3] = t1;
        }
        __syncthreads();   // S5: partials ready

        // ---- Phase E: rpe recompute (f32x2) + channel-wise online softmax + aggregation ----
        {
            unsigned long long r2[4] = {0ull, 0ull, 0ull, 0ull};
            #pragma unroll 4
            for (int k = 0; k < 64; ++k) {
                float wv = sPW2[k * 64 + d_e];
                unsigned long long wp = pack2(wv, wv);
                const ulonglong2* hp = reinterpret_cast<const ulonglong2*>(sH + k * 68 + j0E);
                ulonglong2 ha = hp[0], hb = hp[1];
                r2[0] = ffma2(wp, ha.x, r2[0]);
                r2[1] = ffma2(wp, ha.y, r2[1]);
                r2[2] = ffma2(wp, hb.x, r2[2]);
                r2[3] = ffma2(wp, hb.y, r2[3]);
            }
            float rv[8];
            #pragma unroll
            for (int q = 0; q < 4; ++q) unpack2(r2[q], rv[q * 2], rv[q * 2 + 1]);
            #pragma unroll
            for (int jj = 0; jj < 8; ++jj) {
                int j = j0E + jj;
                float s  = sHid[j * 68 + d_e] + sHid[4352 + j * 68 + d_e];
                float vv = __ldg(g_vp + (size_t)(jbase + j) * 64 + d_e) + rv[jj];
                float mn = fmaxf(m_run, s);
                float cs = __expf(m_run - mn);
                float pe = __expf(s - mn);
                l_run   = fmaf(l_run, cs, pe);
                num_run = fmaf(num_run, cs, pe * vv);
                m_run   = mn;
            }
        }
    }

    // ---- final cross-jsub merge (reuse sH as scratch) ----
    __syncthreads();
    float* sRed = sH;
    sRed[jsub * 64 + d_e]        = m_run;
    sRed[512 + jsub * 64 + d_e]  = l_run;
    sRed[1024 + jsub * 64 + d_e] = num_run;
    __syncthreads();
    if (tid < 64) {
        float M = -CUDART_INF_F;
        #pragma unroll
        for (int s2 = 0; s2 < 8; ++s2) M = fmaxf(M, sRed[s2 * 64 + tid]);
        float L = 0.f, NU = 0.f;
        #pragma unroll
        for (int s2 = 0; s2 < 8; ++s2) {
            float e = __expf(sRed[s2 * 64 + tid] - M);
            L  = fmaf(sRed[512 + s2 * 64 + tid], e, L);
            NU = fmaf(sRed[1024 + s2 * 64 + tid], e, NU);
        }
        out[i * 64 + tid] = NU / L;
    }
}

// ---------------- launch ----------------
extern "C" void kernel_launch(void* const* d_in, const int* in_sizes, int n_in,
                              void* d_out, int out_size) {
    const float* x   = (const float*)d_in[0];
    const float* pos = (const float*)d_in[1];
    const float* Wq  = (const float*)d_in[2];
    const float* Wk  = (const float*)d_in[3];
    const float* Wv  = (const float*)d_in[4];
    const float* pW1 = (const float*)d_in[5];
    const float* pb1 = (const float*)d_in[6];
    const float* pW2 = (const float*)d_in[7];
    const float* pb2 = (const float*)d_in[8];
    const float* aW1 = (const float*)d_in[9];
    const float* ab1 = (const float*)d_in[10];
    const float* aW2 = (const float*)d_in[11];
    // d_in[12] = ab2: constant over j per channel -> cancels in softmax (exact), unused.
    float* out = (float*)d_out;

    cudaFuncSetAttribute(pt_main, cudaFuncAttributeMaxDynamicSharedMemorySize, SMEM_BYTES);

    prep_pw2a<<<64, 256>>>(pW2, aW1);
    prep_qkv<<<NPTS, 256>>>(x, Wq, Wk, Wv, aW1, ab1, pb2);
    pt_main<<<NPTS, 512, SMEM_BYTES>>>(pos, pW1, pb1, pW2, aW2, out);
}

// round 8
// speedup vs baseline: 1.6113x; 1.6113x over previous
#include <cuda_runtime.h>
#include <cuda_bf16.h>
#include <mma.h>
#include <math_constants.h>
#include <cstdint>

using namespace nvcuda;

#define NPTS 1024
#define HA   256

// ---------------- persistent device scratch ----------------
__device__ float g_qa[NPTS * HA];
__device__ float g_ka[NPTS * HA];
__device__ float g_vp[NPTS * 64];
__device__ float g_pW2a[64 * HA];
// bf16 hi/lo split weights (original row-major layouts)
__device__ __nv_bfloat16 g_w1hi[64 * 256], g_w1lo[64 * 256];   // pW2a [k][n]
__device__ __nv_bfloat16 g_wphi[64 * 64],  g_wplo[64 * 64];    // pW2  [k][d]
__device__ __nv_bfloat16 g_w2hi[256 * 64], g_w2lo[256 * 64];   // aW2  [n][d]

__device__ __forceinline__ void split2(float x, __nv_bfloat16& h, __nv_bfloat16& l) {
    h = __float2bfloat16(x);
    l = __float2bfloat16(x - __bfloat162float(h));
}
__device__ __forceinline__ uint32_t pack_bf2(__nv_bfloat16 a, __nv_bfloat16 b) {
    __nv_bfloat162 t; t.x = a; t.y = b;
    return *reinterpret_cast<uint32_t*>(&t);
}

// ---------------- prep kernels ----------------
__global__ void prep_pw2a(const float* __restrict__ pW2, const float* __restrict__ aW1) {
    int k = blockIdx.x, n = threadIdx.x;
    float s = 0.f;
    #pragma unroll 16
    for (int c = 0; c < 64; ++c) s = fmaf(pW2[k * 64 + c], aW1[c * 256 + n], s);
    g_pW2a[k * 256 + n] = s;
}

__global__ void prep_qkv(const float* __restrict__ x,  const float* __restrict__ Wq,
                         const float* __restrict__ Wk, const float* __restrict__ Wv,
                         const float* __restrict__ aW1, const float* __restrict__ ab1,
                         const float* __restrict__ pb2) {
    __shared__ float sx[64], sq[64], sk[64];
    int i = blockIdx.x, t = threadIdx.x;
    if (t < 64) sx[t] = x[i * 64 + t];
    __syncthreads();
    if (t < 64) {
        float aq = 0.f, ak = 0.f, av = 0.f;
        #pragma unroll 16
        for (int c = 0; c < 64; ++c) {
            float xc = sx[c];
            aq = fmaf(xc, Wq[c * 64 + t], aq);
            ak = fmaf(xc, Wk[c * 64 + t], ak);
            av = fmaf(xc, Wv[c * 64 + t], av);
        }
        sq[t] = aq; sk[t] = ak;
        g_vp[i * 64 + t] = av + pb2[t];
    }
    __syncthreads();
    int n = t;
    float accq = 0.f, acck = 0.f, accb = 0.f;
    #pragma unroll 8
    for (int c = 0; c < 64; ++c) {
        float w = aW1[c * 256 + n];
        accq = fmaf(sq[c], w, accq);
        acck = fmaf(sk[c], w, acck);
        accb = fmaf(pb2[c], w, accb);
    }
    g_qa[i * HA + n] = accq + ab1[n] + accb;
    g_ka[i * HA + n] = acck;
}

__global__ void prep_wsplit(const float* __restrict__ pW2, const float* __restrict__ aW2) {
    int t = blockIdx.x * 256 + threadIdx.x;   // grid 64 -> 0..16383
    {
        __nv_bfloat16 h, l; split2(g_pW2a[t], h, l);
        g_w1hi[t] = h; g_w1lo[t] = l;
    }
    if (t < 4096) {
        __nv_bfloat16 h, l; split2(pW2[t], h, l);
        g_wphi[t] = h; g_wplo[t] = l;
    }
    {
        __nv_bfloat16 h, l; split2(aW2[t], h, l);
        g_w2hi[t] = h; g_w2lo[t] = l;
    }
}

// ---------------- smem byte offsets ----------------
#define SM_W1HI 0u         /* 64 x 264 bf16 = 33792 */
#define SM_W1LO 33792u
#define SM_WPHI 67584u     /* 64 x 72 bf16 = 9216 */
#define SM_WPLO 76800u
#define SM_W2HI 86016u     /* 256 x 72 bf16 = 36864 */
#define SM_W2LO 122880u
#define SM_HHI  159744u    /* 64 x 72 bf16 = 9216 */
#define SM_HLO  168960u
#define SM_G1   178176u    /* 64 x 68 f32 = 17408 */
#define SM_HIDH 195584u    /* 64 x 72 bf16 */
#define SM_HIDL 204800u
#define SM_QA   214016u    /* 256 f32 */
#define SMEM_BYTES 215040u
// end-of-chunk overlays (regions dead by then)
#define SM_SIM  SM_HHI     /* 64 x 68 f32 over Hhi/Hlo */
#define SM_RPE  SM_G1      /* 64 x 68 f32 over G1 */

extern __shared__ char smc[];

__global__ __launch_bounds__(512, 1)
void pt_main(const float* __restrict__ pos, const float* __restrict__ pW1,
             const float* __restrict__ pb1, float* __restrict__ out) {
    const int i = blockIdx.x, tid = threadIdx.x;
    const int wid = tid >> 5;

    __nv_bfloat16* sW1hi = (__nv_bfloat16*)(smc + SM_W1HI);
    __nv_bfloat16* sW1lo = (__nv_bfloat16*)(smc + SM_W1LO);
    __nv_bfloat16* sWphi = (__nv_bfloat16*)(smc + SM_WPHI);
    __nv_bfloat16* sWplo = (__nv_bfloat16*)(smc + SM_WPLO);
    __nv_bfloat16* sW2hi = (__nv_bfloat16*)(smc + SM_W2HI);
    __nv_bfloat16* sW2lo = (__nv_bfloat16*)(smc + SM_W2LO);
    __nv_bfloat16* sHhi  = (__nv_bfloat16*)(smc + SM_HHI);
    __nv_bfloat16* sHlo  = (__nv_bfloat16*)(smc + SM_HLO);
    float* sG1  = (float*)(smc + SM_G1);
    __nv_bfloat16* sHidh = (__nv_bfloat16*)(smc + SM_HIDH);
    __nv_bfloat16* sHidl = (__nv_bfloat16*)(smc + SM_HIDL);
    float* sQa  = (float*)(smc + SM_QA);
    float* sSim = (float*)(smc + SM_SIM);
    float* sRpe = (float*)(smc + SM_RPE);

    // ---- stage weights (8B-vector copies into padded strides) ----
    {   // W1: 64x256 -> stride 264
        const ulonglong1* s1 = (const ulonglong1*)g_w1hi;
        const ulonglong1* s2 = (const ulonglong1*)g_w1lo;
        for (int u = tid; u < 64 * 64; u += 512) {
            int r = u >> 6, c4 = (u & 63) * 4;
            *(unsigned long long*)(sW1hi + r * 264 + c4) = s1[u].x;
            *(unsigned long long*)(sW1lo + r * 264 + c4) = s2[u].x;
        }
    }
    {   // Wp: 64x64 -> stride 72
        const ulonglong1* s1 = (const ulonglong1*)g_wphi;
        const ulonglong1* s2 = (const ulonglong1*)g_wplo;
        for (int u = tid; u < 64 * 16; u += 512) {
            int r = u >> 4, c4 = (u & 15) * 4;
            *(unsigned long long*)(sWphi + r * 72 + c4) = s1[u].x;
            *(unsigned long long*)(sWplo + r * 72 + c4) = s2[u].x;
        }
    }
    {   // W2: 256x64 -> stride 72
        const ulonglong1* s1 = (const ulonglong1*)g_w2hi;
        const ulonglong1* s2 = (const ulonglong1*)g_w2lo;
        for (int u = tid; u < 256 * 16; u += 512) {
            int r = u >> 4, c4 = (u & 15) * 4;
            *(unsigned long long*)(sW2hi + r * 72 + c4) = s1[u].x;
            *(unsigned long long*)(sW2lo + r * 72 + c4) = s2[u].x;
        }
    }
    for (int t = tid; t < 256; t += 512) sQa[t] = g_qa[i * 256 + t];
    __shared__ float sPW1[128], sPb1[64];
    if (tid < 128) sPW1[tid] = pW1[tid];
    if (tid < 64)  sPb1[tid] = pb1[tid];

    const float pix = __ldg(pos + i * 2 + 0);
    const float piy = __ldg(pos + i * 2 + 1);

    // warp tile mapping (all GEMMs produce 64x64 per phase): 4x4 warp grid
    const int mr = wid >> 2;      // row block (16 rows)
    const int nc = wid & 3;       // col block (16 cols)
    // elementwise mappings
    const int jT = tid >> 3, c0T = (tid & 7) * 8;   // 8 elems per thread over 64x64
    const int d_e = tid & 63, jg = tid >> 6;        // softmax: 8 j per thread

    float m_run = -CUDART_INF_F, l_run = 0.f, num_run = 0.f;

    wmma::fragment<wmma::matrix_a, 16, 16, 16, __nv_bfloat16, wmma::row_major> afh, afl;
    wmma::fragment<wmma::matrix_b, 16, 16, 16, __nv_bfloat16, wmma::row_major> bfh, bfl;
    wmma::fragment<wmma::accumulator, 16, 16, 16, float> acc, simAcc, rpeAcc;

    __syncthreads();   // staging complete

    for (int c = 0; c < 16; ++c) {
        const int jbase = c * 64;

        // ---- Phase A: H[j][k] hi/lo bf16, stride 72 ----
        {
            float2 pj = __ldg(reinterpret_cast<const float2*>(pos + (jbase + jT) * 2));
            float dx = pix - pj.x, dy = piy - pj.y;
            uint32_t ph[4], pl[4];
            #pragma unroll
            for (int t = 0; t < 8; t += 2) {
                int k0 = c0T + t;
                float h0 = fmaxf(fmaf(dx, sPW1[k0],     fmaf(dy, sPW1[64 + k0],     sPb1[k0])),     0.f);
                float h1 = fmaxf(fmaf(dx, sPW1[k0 + 1], fmaf(dy, sPW1[64 + k0 + 1], sPb1[k0 + 1])), 0.f);
                __nv_bfloat16 a, b, al, bl;
                split2(h0, a, al); split2(h1, b, bl);
                ph[t >> 1] = pack_bf2(a, b);
                pl[t >> 1] = pack_bf2(al, bl);
            }
            *reinterpret_cast<uint4*>(sHhi + jT * 72 + c0T) = make_uint4(ph[0], ph[1], ph[2], ph[3]);
            *reinterpret_cast<uint4*>(sHlo + jT * 72 + c0T) = make_uint4(pl[0], pl[1], pl[2], pl[3]);
        }
        __syncthreads();   // H ready

        // ---- rpe GEMM: H @ pW2 -> rpeAcc (held in fragments) ----
        wmma::fill_fragment(rpeAcc, 0.f);
        #pragma unroll
        for (int k = 0; k < 4; ++k) {
            wmma::load_matrix_sync(afh, sHhi + mr * 16 * 72 + k * 16, 72);
            wmma::load_matrix_sync(afl, sHlo + mr * 16 * 72 + k * 16, 72);
            wmma::load_matrix_sync(bfh, sWphi + k * 16 * 72 + nc * 16, 72);
            wmma::load_matrix_sync(bfl, sWplo + k * 16 * 72 + nc * 16, 72);
            wmma::mma_sync(rpeAcc, afh, bfh, rpeAcc);
            wmma::mma_sync(rpeAcc, afl, bfh, rpeAcc);
            wmma::mma_sync(rpeAcc, afh, bfl, rpeAcc);
        }

        wmma::fill_fragment(simAcc, 0.f);

        // ---- 4 quarters: GEMM1 (n-slice) -> epilogue -> GEMM2 accumulate ----
        for (int q = 0; q < 4; ++q) {
            const int n0 = q * 64;
            // GEMM1 quarter
            wmma::fill_fragment(acc, 0.f);
            #pragma unroll
            for (int k = 0; k < 4; ++k) {
                wmma::load_matrix_sync(afh, sHhi + mr * 16 * 72 + k * 16, 72);
                wmma::load_matrix_sync(afl, sHlo + mr * 16 * 72 + k * 16, 72);
                wmma::load_matrix_sync(bfh, sW1hi + k * 16 * 264 + n0 + nc * 16, 264);
                wmma::load_matrix_sync(bfl, sW1lo + k * 16 * 264 + n0 + nc * 16, 264);
                wmma::mma_sync(acc, afh, bfh, acc);
                wmma::mma_sync(acc, afl, bfh, acc);
                wmma::mma_sync(acc, afh, bfl, acc);
            }
            wmma::store_matrix_sync(sG1 + mr * 16 * 68 + nc * 16, acc, 68, wmma::mem_row_major);
            __syncthreads();

            // epilogue: + qa - ka, relu, re-split -> Hid
            {
                float4 g4a = *reinterpret_cast<const float4*>(sG1 + jT * 68 + c0T);
                float4 g4b = *reinterpret_cast<const float4*>(sG1 + jT * 68 + c0T + 4);
                float4 q4a = *reinterpret_cast<const float4*>(sQa + n0 + c0T);
                float4 q4b = *reinterpret_cast<const float4*>(sQa + n0 + c0T + 4);
                const float4* kap = reinterpret_cast<const float4*>(g_ka + (size_t)(jbase + jT) * 256 + n0 + c0T);
                float4 k4a = __ldg(kap), k4b = __ldg(kap + 1);
                float v[8];
                v[0] = fmaxf(g4a.x + q4a.x - k4a.x, 0.f);
                v[1] = fmaxf(g4a.y + q4a.y - k4a.y, 0.f);
                v[2] = fmaxf(g4a.z + q4a.z - k4a.z, 0.f);
                v[3] = fmaxf(g4a.w + q4a.w - k4a.w, 0.f);
                v[4] = fmaxf(g4b.x + q4b.x - k4b.x, 0.f);
                v[5] = fmaxf(g4b.y + q4b.y - k4b.y, 0.f);
                v[6] = fmaxf(g4b.z + q4b.z - k4b.z, 0.f);
                v[7] = fmaxf(g4b.w + q4b.w - k4b.w, 0.f);
                uint32_t ph[4], pl[4];
                #pragma unroll
                for (int t = 0; t < 4; ++t) {
                    __nv_bfloat16 a, b, al, bl;
                    split2(v[t * 2], a, al); split2(v[t * 2 + 1], b, bl);
                    ph[t] = pack_bf2(a, b); pl[t] = pack_bf2(al, bl);
                }
                *reinterpret_cast<uint4*>(sHidh + jT * 72 + c0T) = make_uint4(ph[0], ph[1], ph[2], ph[3]);
                *reinterpret_cast<uint4*>(sHidl + jT * 72 + c0T) = make_uint4(pl[0], pl[1], pl[2], pl[3]);
            }
            __syncthreads();

            // GEMM2 partial: Hid @ W2[n0..n0+64) -> simAcc
            #pragma unroll
            for (int k = 0; k < 4; ++k) {
                wmma::load_matrix_sync(afh, sHidh + mr * 16 * 72 + k * 16, 72);
                wmma::load_matrix_sync(afl, sHidl + mr * 16 * 72 + k * 16, 72);
                wmma::load_matrix_sync(bfh, sW2hi + (n0 + k * 16) * 72 + nc * 16, 72);
                wmma::load_matrix_sync(bfl, sW2lo + (n0 + k * 16) * 72 + nc * 16, 72);
                wmma::mma_sync(simAcc, afh, bfh, simAcc);
                wmma::mma_sync(simAcc, afl, bfh, simAcc);
                wmma::mma_sync(simAcc, afh, bfl, simAcc);
            }
            __syncthreads();   // Hid + G1 free for next quarter
        }

        // ---- store sim/rpe to overlaid scratch (H & G1 dead now) ----
        wmma::store_matrix_sync(sSim + mr * 16 * 68 + nc * 16, simAcc, 68, wmma::mem_row_major);
        wmma::store_matrix_sync(sRpe + mr * 16 * 68 + nc * 16, rpeAcc, 68, wmma::mem_row_major);
        __syncthreads();

        // ---- channel-wise online softmax over 64 j ----
        #pragma unroll
        for (int jj = 0; jj < 8; ++jj) {
            int j = jg * 8 + jj;
            float s  = sSim[j * 68 + d_e];
            float vv = __ldg(g_vp + (size_t)(jbase + j) * 64 + d_e) + sRpe[j * 68 + d_e];
            float mn = fmaxf(m_run, s);
            float cs = __expf(m_run - mn);
            float pe = __expf(s - mn);
            l_run   = fmaf(l_run, cs, pe);
            num_run = fmaf(num_run, cs, pe * vv);
            m_run   = mn;
        }
        __syncthreads();   // softmax reads done; scratch reusable next chunk
    }

    // ---- final cross-group merge (reuse sSim region) ----
    float* sRed = sSim;
    sRed[jg * 64 + d_e]        = m_run;
    sRed[512 + jg * 64 + d_e]  = l_run;
    sRed[1024 + jg * 64 + d_e] = num_run;
    __syncthreads();
    if (tid < 64) {
        float M = -CUDART_INF_F;
        #pragma unroll
        for (int s2 = 0; s2 < 8; ++s2) M = fmaxf(M, sRed[s2 * 64 + tid]);
        float L = 0.f, NU = 0.f;
        #pragma unroll
        for (int s2 = 0; s2 < 8; ++s2) {
            float e = __expf(sRed[s2 * 64 + tid] - M);
            L  = fmaf(sRed[512 + s2 * 64 + tid], e, L);
            NU = fmaf(sRed[1024 + s2 * 64 + tid], e, NU);
        }
        out[i * 64 + tid] = NU / L;
    }
}

// ---------------- launch ----------------
extern "C" void kernel_launch(void* const* d_in, const int* in_sizes, int n_in,
                              void* d_out, int out_size) {
    const float* x   = (const float*)d_in[0];
    const float* pos = (const float*)d_in[1];
    const float* Wq  = (const float*)d_in[2];
    const float* Wk  = (const float*)d_in[3];
    const float* Wv  = (const float*)d_in[4];
    const float* pW1 = (const float*)d_in[5];
    const float* pb1 = (const float*)d_in[6];
    const float* pW2 = (const float*)d_in[7];
    const float* pb2 = (const float*)d_in[8];
    const float* aW1 = (const float*)d_in[9];
    const float* ab1 = (const float*)d_in[10];
    const float* aW2 = (const float*)d_in[11];
    // d_in[12] = ab2: constant over j per channel -> cancels in softmax (exact), unused.
    float* out = (float*)d_out;

    cudaFuncSetAttribute(pt_main, cudaFuncAttributeMaxDynamicSharedMemorySize, SMEM_BYTES);

    prep_pw2a<<<64, 256>>>(pW2, aW1);
    prep_qkv<<<NPTS, 256>>>(x, Wq, Wk, Wv, aW1, ab1, pb2);
    prep_wsplit<<<64, 256>>>(pW2, aW2);
    pt_main<<<NPTS, 512, SMEM_BYTES>>>(pos, pW1, pb1, out);
}

// round 9
// speedup vs baseline: 1.8238x; 1.1318x over previous
#include <cuda_runtime.h>
#include <cuda_bf16.h>
#include <mma.h>
#include <math_constants.h>
#include <cstdint>

using namespace nvcuda;

#define NPTS 1024
#define HA   256

// ---------------- persistent device scratch ----------------
__device__ float g_qa[NPTS * HA];
__device__ float g_ka[NPTS * HA];
__device__ float g_vp[NPTS * 64];
__device__ float g_pW2a[64 * HA];
__device__ __nv_bfloat16 g_w1hi[64 * 256], g_w1lo[64 * 256];   // pW2a [k][n]
__device__ __nv_bfloat16 g_wphi[64 * 64],  g_wplo[64 * 64];    // pW2  [k][d]
__device__ __nv_bfloat16 g_w2Thi[64 * 256], g_w2Tlo[64 * 256]; // aW2^T [d][n]

__device__ __forceinline__ void split2(float x, __nv_bfloat16& h, __nv_bfloat16& l) {
    h = __float2bfloat16(x);
    l = __float2bfloat16(x - __bfloat162float(h));
}
__device__ __forceinline__ uint32_t pack_bf2(__nv_bfloat16 a, __nv_bfloat16 b) {
    __nv_bfloat162 t; t.x = a; t.y = b;
    return *reinterpret_cast<uint32_t*>(&t);
}

// ---------------- prep kernels ----------------
__global__ void prep_pw2a(const float* __restrict__ pW2, const float* __restrict__ aW1) {
    int k = blockIdx.x, n = threadIdx.x;
    float s = 0.f;
    #pragma unroll 16
    for (int c = 0; c < 64; ++c) s = fmaf(pW2[k * 64 + c], aW1[c * 256 + n], s);
    g_pW2a[k * 256 + n] = s;
}

__global__ void prep_qkv(const float* __restrict__ x,  const float* __restrict__ Wq,
                         const float* __restrict__ Wk, const float* __restrict__ Wv,
                         const float* __restrict__ aW1, const float* __restrict__ ab1,
                         const float* __restrict__ pb2) {
    __shared__ float sx[64], sq[64], sk[64];
    int i = blockIdx.x, t = threadIdx.x;
    if (t < 64) sx[t] = x[i * 64 + t];
    __syncthreads();
    if (t < 64) {
        float aq = 0.f, ak = 0.f, av = 0.f;
        #pragma unroll 16
        for (int c = 0; c < 64; ++c) {
            float xc = sx[c];
            aq = fmaf(xc, Wq[c * 64 + t], aq);
            ak = fmaf(xc, Wk[c * 64 + t], ak);
            av = fmaf(xc, Wv[c * 64 + t], av);
        }
        sq[t] = aq; sk[t] = ak;
        g_vp[i * 64 + t] = av + pb2[t];
    }
    __syncthreads();
    int n = t;
    float accq = 0.f, acck = 0.f, accb = 0.f;
    #pragma unroll 8
    for (int c = 0; c < 64; ++c) {
        float w = aW1[c * 256 + n];
        accq = fmaf(sq[c], w, accq);
        acck = fmaf(sk[c], w, acck);
        accb = fmaf(pb2[c], w, accb);
    }
    g_qa[i * HA + n] = accq + ab1[n] + accb;
    g_ka[i * HA + n] = acck;
}

__global__ void prep_wsplit(const float* __restrict__ pW2, const float* __restrict__ aW2) {
    int t = blockIdx.x * 256 + threadIdx.x;   // grid 64 -> 0..16383
    {
        __nv_bfloat16 h, l; split2(g_pW2a[t], h, l);
        g_w1hi[t] = h; g_w1lo[t] = l;
    }
    if (t < 4096) {
        __nv_bfloat16 h, l; split2(pW2[t], h, l);
        g_wphi[t] = h; g_wplo[t] = l;
    }
    {
        int d = t >> 8, n = t & 255;   // W2T[d][n] = aW2[n][d]
        __nv_bfloat16 h, l; split2(aW2[n * 64 + d], h, l);
        g_w2Thi[t] = h; g_w2Tlo[t] = l;
    }
}

// ---------------- smem byte offsets ----------------
#define SM_W1HI  0u        /* 64 x 264 bf16 = 33792 */
#define SM_W1LO  33792u
#define SM_WPHI  67584u    /* 64 x 72 bf16 = 9216 */
#define SM_WPLO  76800u
#define SM_W2THI 86016u    /* 64 x 264 bf16 = 33792 */
#define SM_W2TLO 119808u
#define SM_HHI   153600u   /* 64 x 72 bf16 = 9216 */
#define SM_HLO   162816u
#define SM_G1    172032u   /* 64 x 136 f32 = 34816 (strip pair / sim partials) */
#define SM_HIDH  206848u   /* 64 x 72 bf16 = 9216 */
#define SM_HIDL  216064u
#define SM_QA    225280u   /* 256 f32 */
#define SMEM_BYTES 226304u
#define SM_RPE   SM_HIDH   /* 64 x 68 f32 overlay (Hid dead by then) */

extern __shared__ char smc[];

__global__ __launch_bounds__(512, 1)
void pt_main(const float* __restrict__ pos, const float* __restrict__ pW1,
             const float* __restrict__ pb1, float* __restrict__ out) {
    const int i = blockIdx.x, tid = threadIdx.x;
    const int wid = tid >> 5;

    __nv_bfloat16* sW1hi = (__nv_bfloat16*)(smc + SM_W1HI);
    __nv_bfloat16* sW1lo = (__nv_bfloat16*)(smc + SM_W1LO);
    __nv_bfloat16* sWphi = (__nv_bfloat16*)(smc + SM_WPHI);
    __nv_bfloat16* sWplo = (__nv_bfloat16*)(smc + SM_WPLO);
    __nv_bfloat16* sW2hi = (__nv_bfloat16*)(smc + SM_W2THI);
    __nv_bfloat16* sW2lo = (__nv_bfloat16*)(smc + SM_W2TLO);
    __nv_bfloat16* sHhi  = (__nv_bfloat16*)(smc + SM_HHI);
    __nv_bfloat16* sHlo  = (__nv_bfloat16*)(smc + SM_HLO);
    float* sG1  = (float*)(smc + SM_G1);
    __nv_bfloat16* sHidh = (__nv_bfloat16*)(smc + SM_HIDH);
    __nv_bfloat16* sHidl = (__nv_bfloat16*)(smc + SM_HIDL);
    float* sQa  = (float*)(smc + SM_QA);
    float* sRpe = (float*)(smc + SM_RPE);

    // ---- stage weights ----
    {   // W1: 64x256 -> stride 264
        const unsigned long long* s1 = (const unsigned long long*)g_w1hi;
        const unsigned long long* s2 = (const unsigned long long*)g_w1lo;
        for (int u = tid; u < 64 * 64; u += 512) {
            int r = u >> 6, c4 = (u & 63) * 4;
            *(unsigned long long*)(sW1hi + r * 264 + c4) = s1[u];
            *(unsigned long long*)(sW1lo + r * 264 + c4) = s2[u];
        }
    }
    {   // Wp: 64x64 -> stride 72
        const unsigned long long* s1 = (const unsigned long long*)g_wphi;
        const unsigned long long* s2 = (const unsigned long long*)g_wplo;
        for (int u = tid; u < 64 * 16; u += 512) {
            int r = u >> 4, c4 = (u & 15) * 4;
            *(unsigned long long*)(sWphi + r * 72 + c4) = s1[u];
            *(unsigned long long*)(sWplo + r * 72 + c4) = s2[u];
        }
    }
    {   // W2T: 64x256 -> stride 264
        const unsigned long long* s1 = (const unsigned long long*)g_w2Thi;
        const unsigned long long* s2 = (const unsigned long long*)g_w2Tlo;
        for (int u = tid; u < 64 * 64; u += 512) {
            int r = u >> 6, c4 = (u & 63) * 4;
            *(unsigned long long*)(sW2hi + r * 264 + c4) = s1[u];
            *(unsigned long long*)(sW2lo + r * 264 + c4) = s2[u];
        }
    }
    for (int t = tid; t < 256; t += 512) sQa[t] = g_qa[i * 256 + t];
    __shared__ float sPW1[128], sPb1[64];
    if (tid < 128) sPW1[tid] = pW1[tid];
    if (tid < 64)  sPb1[tid] = pb1[tid];

    const float pix = __ldg(pos + i * 2 + 0);
    const float piy = __ldg(pos + i * 2 + 1);

    // warp mappings: sg/kg = warp group, wm = m-half (32 rows), wn = n-quarter (16 cols)
    const int sg = wid >> 3;            // GEMM1: strip-in-pair; GEMM2: k-half
    const int wm = (wid >> 2) & 1;
    const int wn = wid & 3;
    // elementwise mappings
    const int jT = tid >> 3, c0T = (tid & 7) * 8;
    const int d_e = tid & 63, jg = tid >> 6;

    float m_run = -CUDART_INF_F, l_run = 0.f, num_run = 0.f;

    wmma::fragment<wmma::matrix_a, 16, 16, 16, __nv_bfloat16, wmma::row_major> ah0, ah1, al0, al1;
    wmma::fragment<wmma::matrix_b, 16, 16, 16, __nv_bfloat16, wmma::row_major> bfh, bfl;
    wmma::fragment<wmma::matrix_b, 16, 16, 16, __nv_bfloat16, wmma::col_major> cbh, cbl;
    wmma::fragment<wmma::accumulator, 16, 16, 16, float> acc0, acc1, sim0, sim1;

    __syncthreads();

    for (int c = 0; c < 16; ++c) {
        const int jbase = c * 64;

        // ---- Phase A: H[j][k] hi/lo bf16, stride 72 ----
        {
            float2 pj = __ldg(reinterpret_cast<const float2*>(pos + (jbase + jT) * 2));
            float dx = pix - pj.x, dy = piy - pj.y;
            uint32_t ph[4], pl[4];
            #pragma unroll
            for (int t = 0; t < 8; t += 2) {
                int k0 = c0T + t;
                float h0 = fmaxf(fmaf(dx, sPW1[k0],     fmaf(dy, sPW1[64 + k0],     sPb1[k0])),     0.f);
                float h1 = fmaxf(fmaf(dx, sPW1[k0 + 1], fmaf(dy, sPW1[64 + k0 + 1], sPb1[k0 + 1])), 0.f);
                __nv_bfloat16 a, b, al, bl;
                split2(h0, a, al); split2(h1, b, bl);
                ph[t >> 1] = pack_bf2(a, b);
                pl[t >> 1] = pack_bf2(al, bl);
            }
            *reinterpret_cast<uint4*>(sHhi + jT * 72 + c0T) = make_uint4(ph[0], ph[1], ph[2], ph[3]);
            *reinterpret_cast<uint4*>(sHlo + jT * 72 + c0T) = make_uint4(pl[0], pl[1], pl[2], pl[3]);
        }
        __syncthreads();

        wmma::fill_fragment(sim0, 0.f);
        wmma::fill_fragment(sim1, 0.f);

        // ---- 2 strip-pairs: GEMM1 (32x16 warp tiles, 2 strips concurrently) ----
        #pragma unroll 1
        for (int pair = 0; pair < 2; ++pair) {
            const int n0 = (pair * 2 + sg) * 64;
            wmma::fill_fragment(acc0, 0.f);
            wmma::fill_fragment(acc1, 0.f);
            #pragma unroll
            for (int k = 0; k < 4; ++k) {
                wmma::load_matrix_sync(ah0, sHhi + (wm * 32) * 72 + k * 16, 72);
                wmma::load_matrix_sync(ah1, sHhi + (wm * 32 + 16) * 72 + k * 16, 72);
                wmma::load_matrix_sync(al0, sHlo + (wm * 32) * 72 + k * 16, 72);
                wmma::load_matrix_sync(al1, sHlo + (wm * 32 + 16) * 72 + k * 16, 72);
                wmma::load_matrix_sync(bfh, sW1hi + k * 16 * 264 + n0 + wn * 16, 264);
                wmma::load_matrix_sync(bfl, sW1lo + k * 16 * 264 + n0 + wn * 16, 264);
                wmma::mma_sync(acc0, ah0, bfh, acc0);
                wmma::mma_sync(acc0, al0, bfh, acc0);
                wmma::mma_sync(acc0, ah0, bfl, acc0);
                wmma::mma_sync(acc1, ah1, bfh, acc1);
                wmma::mma_sync(acc1, al1, bfh, acc1);
                wmma::mma_sync(acc1, ah1, bfl, acc1);
            }
            wmma::store_matrix_sync(sG1 + (wm * 32) * 136 + sg * 68 + wn * 16, acc0, 136, wmma::mem_row_major);
            wmma::store_matrix_sync(sG1 + (wm * 32 + 16) * 136 + sg * 68 + wn * 16, acc1, 136, wmma::mem_row_major);
            __syncthreads();

            // ---- per strip: epilogue -> Hid, then GEMM2 split-k accumulate ----
            #pragma unroll 1
            for (int half = 0; half < 2; ++half) {
                const int q = pair * 2 + half;
                const int n0q = q * 64;
                {
                    float4 g4a = *reinterpret_cast<const float4*>(sG1 + jT * 136 + half * 68 + c0T);
                    float4 g4b = *reinterpret_cast<const float4*>(sG1 + jT * 136 + half * 68 + c0T + 4);
                    float4 q4a = *reinterpret_cast<const float4*>(sQa + n0q + c0T);
                    float4 q4b = *reinterpret_cast<const float4*>(sQa + n0q + c0T + 4);
                    const float4* kap = reinterpret_cast<const float4*>(g_ka + (size_t)(jbase + jT) * 256 + n0q + c0T);
                    float4 k4a = __ldg(kap), k4b = __ldg(kap + 1);
                    float v[8];
                    v[0] = fmaxf(g4a.x + q4a.x - k4a.x, 0.f);
                    v[1] = fmaxf(g4a.y + q4a.y - k4a.y, 0.f);
                    v[2] = fmaxf(g4a.z + q4a.z - k4a.z, 0.f);
                    v[3] = fmaxf(g4a.w + q4a.w - k4a.w, 0.f);
                    v[4] = fmaxf(g4b.x + q4b.x - k4b.x, 0.f);
                    v[5] = fmaxf(g4b.y + q4b.y - k4b.y, 0.f);
                    v[6] = fmaxf(g4b.z + q4b.z - k4b.z, 0.f);
                    v[7] = fmaxf(g4b.w + q4b.w - k4b.w, 0.f);
                    uint32_t ph[4], pl[4];
                    #pragma unroll
                    for (int t = 0; t < 4; ++t) {
                        __nv_bfloat16 a, b, al, bl;
                        split2(v[t * 2], a, al); split2(v[t * 2 + 1], b, bl);
                        ph[t] = pack_bf2(a, b); pl[t] = pack_bf2(al, bl);
                    }
                    *reinterpret_cast<uint4*>(sHidh + jT * 72 + c0T) = make_uint4(ph[0], ph[1], ph[2], ph[3]);
                    *reinterpret_cast<uint4*>(sHidl + jT * 72 + c0T) = make_uint4(pl[0], pl[1], pl[2], pl[3]);
                }
                __syncthreads();

                // GEMM2: A = Hid rows, k-half = sg; B = W2T col-major
                #pragma unroll
                for (int kf = 0; kf < 2; ++kf) {
                    const int kloc = sg * 32 + kf * 16;
                    const int nglob = n0q + kloc;
                    wmma::load_matrix_sync(ah0, sHidh + (wm * 32) * 72 + kloc, 72);
                    wmma::load_matrix_sync(ah1, sHidh + (wm * 32 + 16) * 72 + kloc, 72);
                    wmma::load_matrix_sync(al0, sHidl + (wm * 32) * 72 + kloc, 72);
                    wmma::load_matrix_sync(al1, sHidl + (wm * 32 + 16) * 72 + kloc, 72);
                    wmma::load_matrix_sync(cbh, sW2hi + (wn * 16) * 264 + nglob, 264);
                    wmma::load_matrix_sync(cbl, sW2lo + (wn * 16) * 264 + nglob, 264);
                    wmma::mma_sync(sim0, ah0, cbh, sim0);
                    wmma::mma_sync(sim0, al0, cbh, sim0);
                    wmma::mma_sync(sim0, ah0, cbl, sim0);
                    wmma::mma_sync(sim1, ah1, cbh, sim1);
                    wmma::mma_sync(sim1, al1, cbh, sim1);
                    wmma::mma_sync(sim1, ah1, cbl, sim1);
                }
                __syncthreads();   // Hid/G1-half reusable
            }
        }

        // ---- strip 4: rpe = H @ pW2 (warps 0-7 only) ----
        if (sg == 0) {
            wmma::fill_fragment(acc0, 0.f);
            wmma::fill_fragment(acc1, 0.f);
            #pragma unroll
            for (int k = 0; k < 4; ++k) {
                wmma::load_matrix_sync(ah0, sHhi + (wm * 32) * 72 + k * 16, 72);
                wmma::load_matrix_sync(ah1, sHhi + (wm * 32 + 16) * 72 + k * 16, 72);
                wmma::load_matrix_sync(al0, sHlo + (wm * 32) * 72 + k * 16, 72);
                wmma::load_matrix_sync(al1, sHlo + (wm * 32 + 16) * 72 + k * 16, 72);
                wmma::load_matrix_sync(bfh, sWphi + k * 16 * 72 + wn * 16, 72);
                wmma::load_matrix_sync(bfl, sWplo + k * 16 * 72 + wn * 16, 72);
                wmma::mma_sync(acc0, ah0, bfh, acc0);
                wmma::mma_sync(acc0, al0, bfh, acc0);
                wmma::mma_sync(acc0, ah0, bfl, acc0);
                wmma::mma_sync(acc1, ah1, bfh, acc1);
                wmma::mma_sync(acc1, al1, bfh, acc1);
                wmma::mma_sync(acc1, ah1, bfl, acc1);
            }
            wmma::store_matrix_sync(sG1 + (wm * 32) * 136 + wn * 16, acc0, 136, wmma::mem_row_major);
            wmma::store_matrix_sync(sG1 + (wm * 32 + 16) * 136 + wn * 16, acc1, 136, wmma::mem_row_major);
        }
        __syncthreads();

        // ---- rpe copy-out (G1 col 0-63 -> sRpe overlay on Hid) ----
        {
            float4 r4a = *reinterpret_cast<const float4*>(sG1 + jT * 136 + c0T);
            float4 r4b = *reinterpret_cast<const float4*>(sG1 + jT * 136 + c0T + 4);
            *reinterpret_cast<float4*>(sRpe + jT * 68 + c0T)     = r4a;
            *reinterpret_cast<float4*>(sRpe + jT * 68 + c0T + 4) = r4b;
        }
        __syncthreads();

        // ---- sim partial stores: k-group sg at G1 cols sg*68 ----
        wmma::store_matrix_sync(sG1 + (wm * 32) * 136 + sg * 68 + wn * 16, sim0, 136, wmma::mem_row_major);
        wmma::store_matrix_sync(sG1 + (wm * 32 + 16) * 136 + sg * 68 + wn * 16, sim1, 136, wmma::mem_row_major);
        __syncthreads();

        // ---- channel-wise online softmax over 64 j ----
        #pragma unroll
        for (int jj = 0; jj < 8; ++jj) {
            int j = jg * 8 + jj;
            float s  = sG1[j * 136 + d_e] + sG1[j * 136 + 68 + d_e];
            float vv = __ldg(g_vp + (size_t)(jbase + j) * 64 + d_e) + sRpe[j * 68 + d_e];
            float mn = fmaxf(m_run, s);
            float cs = __expf(m_run - mn);
            float pe = __expf(s - mn);
            l_run   = fmaf(l_run, cs, pe);
            num_run = fmaf(num_run, cs, pe * vv);
            m_run   = mn;
        }
        __syncthreads();   // scratch reusable next chunk
    }

    // ---- final cross-group merge (reuse G1) ----
    float* sRed = sG1;
    sRed[jg * 64 + d_e]        = m_run;
    sRed[512 + jg * 64 + d_e]  = l_run;
    sRed[1024 + jg * 64 + d_e] = num_run;
    __syncthreads();
    if (tid < 64) {
        float M = -CUDART_INF_F;
        #pragma unroll
        for (int s2 = 0; s2 < 8; ++s2) M = fmaxf(M, sRed[s2 * 64 + tid]);
        float L = 0.f, NU = 0.f;
        #pragma unroll
        for (int s2 = 0; s2 < 8; ++s2) {
            float e = __expf(sRed[s2 * 64 + tid] - M);
            L  = fmaf(sRed[512 + s2 * 64 + tid], e, L);
            NU = fmaf(sRed[1024 + s2 * 64 + tid], e, NU);
        }
        out[i * 64 + tid] = NU / L;
    }
}

// ---------------- launch ----------------
extern "C" void kernel_launch(void* const* d_in, const int* in_sizes, int n_in,
                              void* d_out, int out_size) {
    const float* x   = (const float*)d_in[0];
    const float* pos = (const float*)d_in[1];
    const float* Wq  = (const float*)d_in[2];
    const float* Wk  = (const float*)d_in[3];
    const float* Wv  = (const float*)d_in[4];
    const float* pW1 = (const float*)d_in[5];
    const float* pb1 = (const float*)d_in[6];
    const float* pW2 = (const float*)d_in[7];
    const float* pb2 = (const float*)d_in[8];
    const float* aW1 = (const float*)d_in[9];
    const float* ab1 = (const float*)d_in[10];
    const float* aW2 = (const float*)d_in[11];
    // d_in[12] = ab2: constant over j per channel -> cancels in softmax (exact), unused.
    float* out = (float*)d_out;

    cudaFuncSetAttribute(pt_main, cudaFuncAttributeMaxDynamicSharedMemorySize, SMEM_BYTES);

    prep_pw2a<<<64, 256>>>(pW2, aW1);
    prep_qkv<<<NPTS, 256>>>(x, Wq, Wk, Wv, aW1, ab1, pb2);
    prep_wsplit<<<64, 256>>>(pW2, aW2);
    pt_main<<<NPTS, 512, SMEM_BYTES>>>(pos, pW1, pb1, out);
}